// round 8
// baseline (speedup 1.0000x reference)
#include <cuda_runtime.h>
#include <cuda_fp16.h>
#include <cstdint>
#include <math.h>

// score[b,q] = softmax-weighted mean of logits l[q,s] = Q[q]·S[s].
// fp16 mma.sync GEMM (fp32 accum) + online stats.
// R8: persistent CTAs (304 = 2/SM), 2048 fine-grained work items,
//     pipeline rolls across item boundaries, per-warp partials to gmem.

#define B_   16
#define LQ_  2048
#define LS_  2048
#define D_   512

#define SPLITS 8
#define SRANGE (LS_/SPLITS)   // 256
#define BM 128
#define BN 128
#define BK 64
#define NSTG 3
#define NTILE_S (SRANGE/BN)   // 2
#define NCHUNK_IT 16          // chunks per item = NTILE_S * (D_/BK)
#define THREADS 256
#define NCTA 304
#define NITEMS (SPLITS*B_*(LQ_/BM))   // 2048
#define NWN 4                 // n-warps

#define Q_TILE_BYTES 16384
#define S_TILE_BYTES 16384
#define STAGE_BYTES  (Q_TILE_BYTES + S_TILE_BYTES)   // 32KB
#define SMEM_BYTES   (NSTG*STAGE_BYTES + 1024)       // ~97KB -> 2 CTAs/SM

// ---- device-global scratch (allocation-free) ----
__device__ __half g_Qh[(size_t)B_*LQ_*D_];
__device__ __half g_Sh[(size_t)B_*LS_*D_];
__device__ float g_pm  [SPLITS*NWN*B_*LQ_];
__device__ float g_pse [SPLITS*NWN*B_*LQ_];
__device__ float g_pswe[SPLITS*NWN*B_*LQ_];

#define L2E 1.4426950408889634f

__device__ __forceinline__ float ex2f(float x) {
    float y;
    asm("ex2.approx.ftz.f32 %0, %1;" : "=f"(y) : "f"(x));
    return y;
}
__device__ __forceinline__ uint32_t smem_u32(const void* p) {
    uint32_t a;
    asm("{ .reg .u64 t; cvta.to.shared.u64 t, %1; cvt.u32.u64 %0, t; }" : "=r"(a) : "l"(p));
    return a;
}
__device__ __forceinline__ void ldsm_x4(uint32_t (&r)[4], uint32_t addr) {
    asm volatile("ldmatrix.sync.aligned.m8n8.x4.shared.b16 {%0,%1,%2,%3}, [%4];"
        : "=r"(r[0]), "=r"(r[1]), "=r"(r[2]), "=r"(r[3]) : "r"(addr));
}
__device__ __forceinline__ void mma16816(float (&d)[4], const uint32_t (&a)[4],
                                         const uint32_t* b) {
    asm volatile("mma.sync.aligned.m16n8k16.row.col.f32.f16.f16.f32 "
        "{%0,%1,%2,%3}, {%4,%5,%6,%7}, {%8,%9}, {%0,%1,%2,%3};"
        : "+f"(d[0]), "+f"(d[1]), "+f"(d[2]), "+f"(d[3])
        : "r"(a[0]), "r"(a[1]), "r"(a[2]), "r"(a[3]), "r"(b[0]), "r"(b[1]));
}
#define CP_ASYNC16(dst, src) \
    asm volatile("cp.async.cg.shared.global [%0], [%1], 16;" :: "r"(dst), "l"(src) : "memory")
#define CP_COMMIT() asm volatile("cp.async.commit_group;" ::: "memory")
#define CP_WAIT(n)  asm volatile("cp.async.wait_group %0;" :: "n"(n) : "memory")

__device__ __forceinline__ void merge_stats(float& m, float& se, float& swe,
                                            float om, float ose, float oswe) {
    float nm = fmaxf(m, om);
    float s1 = ex2f((m - nm) * L2E);
    float s2 = ex2f((om - nm) * L2E);
    se  = se  * s1 + ose  * s2;
    swe = swe * s1 + oswe * s2;
    m = nm;
}

// ---------------- conversion pre-pass: fp32 -> fp16 (4 float4/thread) ----------------
__global__ void __launch_bounds__(256)
convert_kernel(const float* __restrict__ Q, const float* __restrict__ S)
{
    const float* src = blockIdx.y ? S : Q;
    __half* dst = blockIdx.y ? g_Sh : g_Qh;
    size_t base = (size_t)blockIdx.x * 1024 + threadIdx.x;
    #pragma unroll
    for (int j = 0; j < 4; ++j) {
        size_t i = base + j * 256;
        float4 v = reinterpret_cast<const float4*>(src)[i];
        __half2 p0{__float2half_rn(v.x), __float2half_rn(v.y)};
        __half2 p1{__float2half_rn(v.z), __float2half_rn(v.w)};
        uint2 pv{*reinterpret_cast<uint32_t*>(&p0), *reinterpret_cast<uint32_t*>(&p1)};
        reinterpret_cast<uint2*>(dst)[i] = pv;
    }
}

// ---------------- persistent fused GEMM + online softmax-weighted-mean ----------------
__global__ void __launch_bounds__(THREADS, 2)
attn_mma_kernel()
{
    extern __shared__ __align__(1024) char smem_raw[];
    const uint32_t sb = (smem_u32(smem_raw) + 1023u) & ~1023u;

    const int tid = threadIdx.x;
    const int wid = tid >> 5, lane = tid & 31;
    const int warp_m = wid & 1;      // 0..1 -> 64 rows each
    const int warp_n = wid >> 1;     // 0..3 -> 32 cols each
    const int cta = blockIdx.x;

    const int my_n = (NITEMS - 1 - cta) / NCTA + 1;   // items for this CTA
    const int total = my_n * NCHUNK_IT;               // global chunk count

    // item decode: item = qt + 16*b + 256*sp  (consecutive CTAs share (sp,b) S-range)
    auto qbase_of = [&](int it) {
        int qt = it & 15, b = (it >> 4) & 15;
        return (b * LQ_ + qt * BM) * D_;
    };
    auto sbase_of = [&](int it) {
        int b = (it >> 4) & 15, sp = it >> 8;
        return (b * LS_ + sp * SRANGE) * D_;
    };

    // ---- chunk loader (one cp.async group per chunk) ----
    auto load_chunk = [&](int g) {
        const int it = cta + (g >> 4) * NCTA;
        const int chunk = g & 15;
        const int stile = chunk >> 3, kof = (chunk & 7) * BK;
        const int qb = qbase_of(it), sbse = sbase_of(it);
        const uint32_t stb = sb + (g % NSTG) * STAGE_BYTES;
        #pragma unroll
        for (int j = 0; j < 8; ++j) {
            const int cc = tid + j * 256;
            const __half* src;
            uint32_t dst;
            if (cc < 1024) {                        // Q tile
                const int row = cc >> 3, ci = cc & 7;
                src = g_Qh + qb + row * D_ + kof + ci * 8;
                dst = stb + row * 128 + ((ci ^ (row & 7)) << 4);
            } else {                                // S tile
                const int s = cc - 1024;
                const int row = s >> 3, ci = s & 7;
                src = g_Sh + sbse + (stile * BN + row) * D_ + kof + ci * 8;
                dst = stb + Q_TILE_BYTES + row * 128 + ((ci ^ (row & 7)) << 4);
            }
            CP_ASYNC16(dst, src);
        }
        CP_COMMIT();
    };

    float acc[4][4][4];
    #pragma unroll
    for (int i = 0; i < 4; i++)
        #pragma unroll
        for (int j = 0; j < 4; j++)
            #pragma unroll
            for (int k = 0; k < 4; k++) acc[i][j][k] = 0.f;

    float mrow[8], serow[8], swerow[8];
    #pragma unroll
    for (int r = 0; r < 8; r++) { mrow[r] = -INFINITY; serow[r] = 0.f; swerow[r] = 0.f; }

    load_chunk(0);
    load_chunk(1);

    const int lr = lane & 15, lc = lane >> 4;

    for (int g = 0; g < total; ++g) {
        if (g == total - 1) { CP_WAIT(0); } else { CP_WAIT(1); }
        __syncthreads();
        if (g + 2 < total) load_chunk(g + 2);

        // ---- compute chunk from stage g%NSTG ----
        {
            const uint32_t sQ = sb + (g % NSTG) * STAGE_BYTES;
            const uint32_t sS = sQ + Q_TILE_BYTES;
            #pragma unroll
            for (int ks = 0; ks < 4; ++ks) {
                uint32_t bh[4][2];
                #pragma unroll
                for (int p = 0; p < 2; ++p) {
                    const int brow = warp_n * 32 + p * 16 + lr;
                    const uint32_t off = brow * 128 + (((ks * 2 + lc) ^ (brow & 7)) << 4);
                    uint32_t r4[4];
                    ldsm_x4(r4, sS + off);
                    bh[p*2][0]   = r4[0]; bh[p*2][1]   = r4[2];
                    bh[p*2+1][0] = r4[1]; bh[p*2+1][1] = r4[3];
                }
                #pragma unroll
                for (int mt = 0; mt < 4; ++mt) {
                    const int arow = warp_m * 64 + mt * 16 + lr;
                    const uint32_t off = arow * 128 + (((ks * 2 + lc) ^ (arow & 7)) << 4);
                    uint32_t ah[4];
                    ldsm_x4(ah, sQ + off);
                    #pragma unroll
                    for (int nt = 0; nt < 4; ++nt)
                        mma16816(acc[mt][nt], ah, bh[nt]);
                }
            }
        }

        // ---- s-tile boundary: fold accums into per-thread online stats ----
        if ((g & 7) == 7) {
            #pragma unroll
            for (int mt = 0; mt < 4; ++mt) {
                #pragma unroll
                for (int h = 0; h < 2; ++h) {
                    const int r = mt * 2 + h;
                    float v[8];
                    #pragma unroll
                    for (int nt = 0; nt < 4; ++nt) {
                        v[nt * 2]     = acc[mt][nt][h * 2];
                        v[nt * 2 + 1] = acc[mt][nt][h * 2 + 1];
                    }
                    float tm = v[0];
                    #pragma unroll
                    for (int j = 1; j < 8; ++j) tm = fmaxf(tm, v[j]);
                    const float nm = fmaxf(mrow[r], tm);
                    const float nm2 = nm * L2E;
                    float pse = 0.f, pswe = 0.f;
                    #pragma unroll
                    for (int j = 0; j < 8; ++j) {
                        float p = ex2f(fmaf(v[j], L2E, -nm2));
                        pse += p;
                        pswe = fmaf(v[j], p, pswe);
                    }
                    const float sc = ex2f(fmaf(mrow[r], L2E, -nm2)); // -inf -> 0
                    serow[r]  = fmaf(serow[r],  sc, pse);
                    swerow[r] = fmaf(swerow[r], sc, pswe);
                    mrow[r] = nm;
                }
            }
            #pragma unroll
            for (int i = 0; i < 4; i++)
                #pragma unroll
                for (int j = 0; j < 4; j++)
                    #pragma unroll
                    for (int k = 0; k < 4; k++) acc[i][j][k] = 0.f;
        }

        // ---- item boundary: quad-merge and write per-warp partials ----
        if ((g & 15) == 15) {
            const int it = cta + (g >> 4) * NCTA;
            const int qt = it & 15, b = (it >> 4) & 15, sp = it >> 8;
            #pragma unroll
            for (int r = 0; r < 8; ++r) {
                float m = mrow[r], se = serow[r], swe = swerow[r];
                #pragma unroll
                for (int o = 1; o < 4; o <<= 1) {
                    float om   = __shfl_xor_sync(0xffffffffu, m,   o);
                    float ose  = __shfl_xor_sync(0xffffffffu, se,  o);
                    float oswe = __shfl_xor_sync(0xffffffffu, swe, o);
                    merge_stats(m, se, swe, om, ose, oswe);
                }
                mrow[r] = m; serow[r] = se; swerow[r] = swe;
            }
            if ((lane & 3) == 0) {
                const int pbase = ((sp * NWN + warp_n) * B_ + b) * LQ_ + qt * BM;
                #pragma unroll
                for (int mt = 0; mt < 4; ++mt)
                    #pragma unroll
                    for (int h = 0; h < 2; ++h) {
                        const int r = mt * 2 + h;
                        const int row = warp_m * 64 + mt * 16 + h * 8 + (lane >> 2);
                        g_pm  [pbase + row] = mrow[r];
                        g_pse [pbase + row] = serow[r];
                        g_pswe[pbase + row] = swerow[r];
                    }
            }
            #pragma unroll
            for (int r = 0; r < 8; ++r) { mrow[r] = -INFINITY; serow[r] = 0.f; swerow[r] = 0.f; }
        }
    }
}

// ---------------- combine: merge SPLITS*NWN partials per row ----------------
__global__ void __launch_bounds__(256)
combine_kernel(float* __restrict__ out)
{
    const int i = blockIdx.x * blockDim.x + threadIdx.x;   // 0 .. B*LQ
    float m = -INFINITY, se = 0.f, swe = 0.f;
    #pragma unroll
    for (int p = 0; p < SPLITS * NWN; ++p) {
        const int idx = p * B_ * LQ_ + i;
        merge_stats(m, se, swe, g_pm[idx], g_pse[idx], g_pswe[idx]);
    }
    out[i] = swe / se;
}

extern "C" void kernel_launch(void* const* d_in, const int* in_sizes, int n_in,
                              void* d_out, int out_size)
{
    const float* Q = (const float*)d_in[0];
    const float* S = (const float*)d_in[1];
    float* out = (float*)d_out;

    {
        dim3 grid((unsigned)(((size_t)B_ * LQ_ * D_ / 4) / 1024), 2);
        convert_kernel<<<grid, 256>>>(Q, S);
    }
    cudaFuncSetAttribute(attn_mma_kernel, cudaFuncAttributeMaxDynamicSharedMemorySize, SMEM_BYTES);
    attn_mma_kernel<<<NCTA, THREADS, SMEM_BYTES>>>();
    combine_kernel<<<(B_ * LQ_) / 256, 256>>>(out);
}

// round 10
// speedup vs baseline: 1.1093x; 1.1093x over previous
#include <cuda_runtime.h>
#include <cuda_fp16.h>
#include <cstdint>
#include <math.h>

// score[b,q] = softmax-weighted mean of logits l[q,s] = Q[q]·S[s].
// fp16 mma.sync GEMM (fp32 accum) + online stats.
// R9: 4 warps x (64x64) register tiles -> A-redundancy 2, crossbar unbound;
//     128 threads, 2 CTAs/SM, 3-stage cp.async pipeline.

#define B_   16
#define LQ_  2048
#define LS_  2048
#define D_   512

#define SPLITS 4
#define SRANGE (LS_/SPLITS)   // 512
#define BM 128
#define BN 128
#define BK 64
#define NSTG 3
#define NTILE_S (SRANGE/BN)   // 4
#define NCHUNK (NTILE_S*(D_/BK))  // 32
#define THREADS 128
#define NWN 2                 // n-warps

#define Q_TILE_BYTES 16384
#define S_TILE_BYTES 16384
#define STAGE_BYTES  (Q_TILE_BYTES + S_TILE_BYTES)   // 32KB
#define SMEM_BYTES   (NSTG*STAGE_BYTES + 1024)       // ~97KB -> 2 CTAs/SM

// ---- device-global scratch (allocation-free) ----
__device__ __half g_Qh[(size_t)B_*LQ_*D_];
__device__ __half g_Sh[(size_t)B_*LS_*D_];
__device__ float g_pm  [SPLITS*NWN*B_*LQ_];
__device__ float g_pse [SPLITS*NWN*B_*LQ_];
__device__ float g_pswe[SPLITS*NWN*B_*LQ_];

#define L2E 1.4426950408889634f

__device__ __forceinline__ float ex2f(float x) {
    float y;
    asm("ex2.approx.ftz.f32 %0, %1;" : "=f"(y) : "f"(x));
    return y;
}
__device__ __forceinline__ uint32_t smem_u32(const void* p) {
    uint32_t a;
    asm("{ .reg .u64 t; cvta.to.shared.u64 t, %1; cvt.u32.u64 %0, t; }" : "=r"(a) : "l"(p));
    return a;
}
__device__ __forceinline__ void ldsm_x4(uint32_t (&r)[4], uint32_t addr) {
    asm volatile("ldmatrix.sync.aligned.m8n8.x4.shared.b16 {%0,%1,%2,%3}, [%4];"
        : "=r"(r[0]), "=r"(r[1]), "=r"(r[2]), "=r"(r[3]) : "r"(addr));
}
__device__ __forceinline__ void mma16816(float (&d)[4], const uint32_t (&a)[4],
                                         const uint32_t* b) {
    asm volatile("mma.sync.aligned.m16n8k16.row.col.f32.f16.f16.f32 "
        "{%0,%1,%2,%3}, {%4,%5,%6,%7}, {%8,%9}, {%0,%1,%2,%3};"
        : "+f"(d[0]), "+f"(d[1]), "+f"(d[2]), "+f"(d[3])
        : "r"(a[0]), "r"(a[1]), "r"(a[2]), "r"(a[3]), "r"(b[0]), "r"(b[1]));
}
#define CP_ASYNC16(dst, src) \
    asm volatile("cp.async.cg.shared.global [%0], [%1], 16;" :: "r"(dst), "l"(src) : "memory")
#define CP_COMMIT() asm volatile("cp.async.commit_group;" ::: "memory")
#define CP_WAIT(n)  asm volatile("cp.async.wait_group %0;" :: "n"(n) : "memory")

__device__ __forceinline__ void merge_stats(float& m, float& se, float& swe,
                                            float om, float ose, float oswe) {
    float nm = fmaxf(m, om);
    float s1 = ex2f((m - nm) * L2E);
    float s2 = ex2f((om - nm) * L2E);
    se  = se  * s1 + ose  * s2;
    swe = swe * s1 + oswe * s2;
    m = nm;
}

// ---------------- conversion pre-pass: fp32 -> fp16 (4 float4/thread) ----------------
__global__ void __launch_bounds__(256)
convert_kernel(const float* __restrict__ Q, const float* __restrict__ S)
{
    const float* src = blockIdx.y ? S : Q;
    __half* dst = blockIdx.y ? g_Sh : g_Qh;
    size_t base = (size_t)blockIdx.x * 1024 + threadIdx.x;
    #pragma unroll
    for (int j = 0; j < 4; ++j) {
        size_t i = base + j * 256;
        float4 v = reinterpret_cast<const float4*>(src)[i];
        __half2 p0{__float2half_rn(v.x), __float2half_rn(v.y)};
        __half2 p1{__float2half_rn(v.z), __float2half_rn(v.w)};
        uint2 pv{*reinterpret_cast<uint32_t*>(&p0), *reinterpret_cast<uint32_t*>(&p1)};
        reinterpret_cast<uint2*>(dst)[i] = pv;
    }
}

// ---------------- fused GEMM + online softmax-weighted-mean ----------------
__global__ void __launch_bounds__(THREADS, 2)
attn_mma_kernel()
{
    extern __shared__ __align__(1024) char smem_raw[];
    const uint32_t sb = (smem_u32(smem_raw) + 1023u) & ~1023u;
    float* stats = reinterpret_cast<float*>(smem_raw);  // reused after pipeline drains

    const int tid = threadIdx.x;
    const int wid = tid >> 5, lane = tid & 31;
    const int warp_m = wid & 1;      // 0..1 -> 64 rows each
    const int warp_n = wid >> 1;     // 0..1 -> 64 cols each
    const int qt = blockIdx.x, b = blockIdx.y, sp = blockIdx.z;

    const int qbase = (b * LQ_ + qt * BM) * D_;
    const int sbase = (b * LS_ + sp * SRANGE) * D_;

    float acc[4][8][4];
    #pragma unroll
    for (int i = 0; i < 4; i++)
        #pragma unroll
        for (int j = 0; j < 8; j++)
            #pragma unroll
            for (int k = 0; k < 4; k++) acc[i][j][k] = 0.f;

    float mrow[8], serow[8], swerow[8];
    #pragma unroll
    for (int r = 0; r < 8; r++) { mrow[r] = -INFINITY; serow[r] = 0.f; swerow[r] = 0.f; }

    // ---- stage loader: 2048 x 16B / 128 threads = 16 per thread ----
    auto load_stage = [&](int chunk, int stg) {
        const int stile = chunk >> 3, kof = (chunk & 7) * BK;
        const uint32_t stb = sb + stg * STAGE_BYTES;
        #pragma unroll
        for (int j = 0; j < 16; ++j) {
            const int cc = tid + j * 128;
            const __half* src;
            uint32_t dst;
            if (cc < 1024) {                        // Q tile: 128 rows x 8 chunks
                const int row = cc >> 3, ci = cc & 7;
                src = g_Qh + qbase + row * D_ + kof + ci * 8;
                dst = stb + row * 128 + ((ci ^ (row & 7)) << 4);
            } else {                                // S tile: 128 rows x 8 chunks
                const int s = cc - 1024;
                const int row = s >> 3, ci = s & 7;
                src = g_Sh + sbase + (stile * BN + row) * D_ + kof + ci * 8;
                dst = stb + Q_TILE_BYTES + row * 128 + ((ci ^ (row & 7)) << 4);
            }
            CP_ASYNC16(dst, src);
        }
        CP_COMMIT();
    };

    load_stage(0, 0);
    load_stage(1, 1);

    const int lr = lane & 15, lc = lane >> 4;

    for (int c = 0; c < NCHUNK; ++c) {
        if (c == NCHUNK - 1) { CP_WAIT(0); } else { CP_WAIT(1); }
        __syncthreads();
        if (c + 2 < NCHUNK) load_stage(c + 2, (c + 2) % NSTG);

        // ---- compute chunk from stage c%NSTG ----
        {
            const uint32_t sQ = sb + (c % NSTG) * STAGE_BYTES;
            const uint32_t sS = sQ + Q_TILE_BYTES;
            #pragma unroll
            for (int ks = 0; ks < 4; ++ks) {
                uint32_t bh[8][2];
                #pragma unroll
                for (int p = 0; p < 4; ++p) {
                    const int brow = warp_n * 64 + p * 16 + lr;
                    const uint32_t off = brow * 128 + (((ks * 2 + lc) ^ (brow & 7)) << 4);
                    uint32_t r4[4];
                    ldsm_x4(r4, sS + off);
                    bh[p*2][0]   = r4[0]; bh[p*2][1]   = r4[2];
                    bh[p*2+1][0] = r4[1]; bh[p*2+1][1] = r4[3];
                }
                #pragma unroll
                for (int mt = 0; mt < 4; ++mt) {
                    const int arow = warp_m * 64 + mt * 16 + lr;
                    const uint32_t off = arow * 128 + (((ks * 2 + lc) ^ (arow & 7)) << 4);
                    uint32_t ah[4];
                    ldsm_x4(ah, sQ + off);
                    #pragma unroll
                    for (int nt = 0; nt < 8; ++nt)
                        mma16816(acc[mt][nt], ah, bh[nt]);
                }
            }
        }

        // ---- s-tile boundary: fold accums into per-thread online stats ----
        if ((c & 7) == 7) {
            #pragma unroll
            for (int mt = 0; mt < 4; ++mt) {
                #pragma unroll
                for (int h = 0; h < 2; ++h) {
                    const int r = mt * 2 + h;
                    float v[16];
                    #pragma unroll
                    for (int nt = 0; nt < 8; ++nt) {
                        v[nt * 2]     = acc[mt][nt][h * 2];
                        v[nt * 2 + 1] = acc[mt][nt][h * 2 + 1];
                    }
                    float tm = v[0];
                    #pragma unroll
                    for (int j = 1; j < 16; ++j) tm = fmaxf(tm, v[j]);
                    const float nm = fmaxf(mrow[r], tm);
                    const float nm2 = nm * L2E;
                    float pse = 0.f, pswe = 0.f;
                    #pragma unroll
                    for (int j = 0; j < 16; ++j) {
                        float p = ex2f(fmaf(v[j], L2E, -nm2));
                        pse += p;
                        pswe = fmaf(v[j], p, pswe);
                    }
                    const float sc = ex2f(fmaf(mrow[r], L2E, -nm2)); // -inf -> 0
                    serow[r]  = fmaf(serow[r],  sc, pse);
                    swerow[r] = fmaf(swerow[r], sc, pswe);
                    mrow[r] = nm;
                }
            }
            #pragma unroll
            for (int i = 0; i < 4; i++)
                #pragma unroll
                for (int j = 0; j < 8; j++)
                    #pragma unroll
                    for (int k = 0; k < 4; k++) acc[i][j][k] = 0.f;
        }
    }

    __syncthreads();

    // ---- combine 4 lanes sharing each row (quad lanes lane&3) ----
    #pragma unroll
    for (int r = 0; r < 8; ++r) {
        float m = mrow[r], se = serow[r], swe = swerow[r];
        #pragma unroll
        for (int o = 1; o < 4; o <<= 1) {
            float om   = __shfl_xor_sync(0xffffffffu, m,   o);
            float ose  = __shfl_xor_sync(0xffffffffu, se,  o);
            float oswe = __shfl_xor_sync(0xffffffffu, swe, o);
            merge_stats(m, se, swe, om, ose, oswe);
        }
        mrow[r] = m; serow[r] = se; swerow[r] = swe;
    }
    if ((lane & 3) == 0) {
        #pragma unroll
        for (int mt = 0; mt < 4; ++mt)
            #pragma unroll
            for (int h = 0; h < 2; ++h) {
                const int r = mt * 2 + h;
                const int row = warp_m * 64 + mt * 16 + h * 8 + (lane >> 2);
                float* st = stats + (row * NWN + warp_n) * 3;
                st[0] = mrow[r]; st[1] = serow[r]; st[2] = swerow[r];
            }
    }
    __syncthreads();

    // ---- combine NWN n-warp partials per row, write split partial to gmem ----
    if (tid < BM) {
        float m = -INFINITY, se = 0.f, swe = 0.f;
        const float* st = stats + tid * NWN * 3;
        #pragma unroll
        for (int wn = 0; wn < NWN; ++wn)
            merge_stats(m, se, swe, st[wn*3], st[wn*3+1], st[wn*3+2]);
        const int idx = (sp * B_ + b) * LQ_ + qt * BM + tid;
        g_pm[idx] = m; g_pse[idx] = se; g_pswe[idx] = swe;
    }
}

// ---------------- split combine ----------------
__global__ void __launch_bounds__(256)
combine_kernel(float* __restrict__ out)
{
    const int i = blockIdx.x * blockDim.x + threadIdx.x;   // 0 .. B*LQ
    float m = -INFINITY, se = 0.f, swe = 0.f;
    #pragma unroll
    for (int sp = 0; sp < SPLITS; ++sp) {
        const int idx = sp * B_ * LQ_ + i;
        merge_stats(m, se, swe, g_pm[idx], g_pse[idx], g_pswe[idx]);
    }
    out[i] = swe / se;
}

extern "C" void kernel_launch(void* const* d_in, const int* in_sizes, int n_in,
                              void* d_out, int out_size)
{
    const float* Q = (const float*)d_in[0];
    const float* S = (const float*)d_in[1];
    float* out = (float*)d_out;

    {
        dim3 grid((unsigned)(((size_t)B_ * LQ_ * D_ / 4) / 1024), 2);
        convert_kernel<<<grid, 256>>>(Q, S);
    }
    cudaFuncSetAttribute(attn_mma_kernel, cudaFuncAttributeMaxDynamicSharedMemorySize, SMEM_BYTES);
    {
        dim3 grid(LQ_ / BM, B_, SPLITS);
        attn_mma_kernel<<<grid, THREADS, SMEM_BYTES>>>();
    }
    combine_kernel<<<(B_ * LQ_) / 256, 256>>>(out);
}